// round 3
// baseline (speedup 1.0000x reference)
#include <cuda_runtime.h>
#include <climits>

// Problem constants (fixed by reference setup_inputs)
#define W       4096
#define CHOFF   (4096 * 4096)
#define NT      31          // ceil((4096-256)/128)+1
#define STRIDE  128
#define NBLOCKS (NT * NT)   // 961 = 31^2
#define NSLOT   31          // exactly 31 blocks per slot

// dstate layout (all max-encoded, init 0 via one memset):
//   [slot*4 + 0] = max(ymax+1)
//   [slot*4 + 1] = max(4096 - ymin)
//   [slot*4 + 2] = max(xmax+1)
//   [slot*4 + 3] = max(4096 - xmin)
//   [124 + slot] = per-slot completion counter
//   [155]        = master counter
#define D_CNT   (NSLOT * 4)
#define D_MST   (NSLOT * 4 + NSLOT)
__device__ int dstate[NSLOT * 4 + NSLOT + 1];

__global__ __launch_bounds__(256, 7) void tile_kernel(
    const float* __restrict__ x,
    const float* __restrict__ gw,
    const float* __restrict__ gauss,
    const float* __restrict__ sobel,
    float* __restrict__ out)
{
    __shared__ float g[7][260];   // gray / bv rows, col halo +-2 (zero pad)
    __shared__ float b[3][258];   // blurred rows, col halo +-1 (zero pad)
    __shared__ int sF[8], sL[8], sMn[8], sMx[8];

    const int tid  = threadIdx.x;
    const int ty   = blockIdx.x / NT;
    const int tx   = blockIdx.x % NT;
    const int y0   = ty * STRIDE;
    const int x0   = tx * STRIDE;
    const int slot = blockIdx.x % NSLOT;

    // ---- issue all 24 global loads up front (max MLP) ----
    const int base = y0 * W + x0 + tid;
    float a0 = x[base];             float b0c = x[base + CHOFF];             float c0 = x[base + 2*CHOFF];
    float a1 = x[base + W];         float b1c = x[base + W + CHOFF];         float c1 = x[base + W + 2*CHOFF];
    float a2 = x[base + 2*W];       float b2c = x[base + 2*W + CHOFF];       float c2 = x[base + 2*W + 2*CHOFF];
    float a3 = x[base + 3*W];       float b3c = x[base + 3*W + CHOFF];       float c3 = x[base + 3*W + 2*CHOFF];
    const int base2 = base + 252 * W;
    float a4 = x[base2];            float b4c = x[base2 + CHOFF];            float c4 = x[base2 + 2*CHOFF];
    float a5 = x[base2 + W];        float b5c = x[base2 + W + CHOFF];        float c5 = x[base2 + W + 2*CHOFF];
    float a6 = x[base2 + 2*W];      float b6c = x[base2 + 2*W + CHOFF];      float c6 = x[base2 + 2*W + 2*CHOFF];
    float a7 = x[base2 + 3*W];      float b7c = x[base2 + 3*W + CHOFF];      float c7 = x[base2 + 3*W + 2*CHOFF];

    const float w0 = gw[0], w1 = gw[1], w2 = gw[2];
    // Separable factors, derived exactly from the inputs:
    //   gauss[a][c] = uv[a] * vh[c] with uv = gauss[:,0]/gauss[0,0] = [1,4,6,4,1]
    //   (small-integer/256 products -> exact in fp32)
    const float ginv = 1.0f / gauss[0];
    const float uv1 = gauss[5]  * ginv;   // 4
    const float uv2 = gauss[10] * ginv;   // 6
    const float uv3 = gauss[15] * ginv;   // 4
    const float uv4 = gauss[20] * ginv;   // 1
    const float vh0 = gauss[0], vh1 = gauss[1], vh2 = gauss[2], vh3 = gauss[3], vh4 = gauss[4];
    const float sh0 = sobel[0], sh1 = sobel[1], sh2 = sobel[2];  // [1,2,1]

    // Static zero halos (per-tile zero padding; never overwritten)
    if (tid < 2) {
        #pragma unroll
        for (int rr = 0; rr < 7; ++rr) { g[rr][tid] = 0.f; g[rr][258 + tid] = 0.f; }
    }
    if (tid == 0) {
        #pragma unroll
        for (int k = 0; k < 3; ++k) { b[k][0] = 0.f; b[k][257] = 0.f; }
    }

    // Gray (fused channel dot)
    float g0 = w0*a0 + w1*b0c + w2*c0;
    float g1 = w0*a1 + w1*b1c + w2*c1;
    float g2 = w0*a2 + w1*b2c + w2*c2;
    float g3 = w0*a3 + w1*b3c + w2*c3;
    float g252 = w0*a4 + w1*b4c + w2*c4;
    float g253 = w0*a5 + w1*b5c + w2*c5;
    float g254 = w0*a6 + w1*b6c + w2*c6;
    float g255 = w0*a7 + w1*b7c + w2*c7;

    // Vertical gauss (zero-pad above row 0 / below row 255), in registers.
    // Only blurred rows 1 and 254 feed E(0)/E(255) (sobel middle row is 0).
    float bv1   = uv1*g0 + uv2*g1 + uv3*g2 + uv4*g3;          // row -1 pad = 0
    float bv254 = 1.f*g252 + uv1*g253 + uv2*g254 + uv3*g255;  // row 256 pad = 0
    // NOTE: uv0 == 1 exactly (gauss[0]/gauss[0]); uv4 == 1 likewise.
    g[0][2 + tid] = bv1;
    g[1][2 + tid] = bv254;
    __syncthreads();

    // Horizontal gauss (col halo already zero)
    float bh1   = vh0*g[0][tid] + vh1*g[0][tid+1] + vh2*g[0][tid+2] + vh3*g[0][tid+3] + vh4*g[0][tid+4];
    float bh254 = vh0*g[1][tid] + vh1*g[1][tid+1] + vh2*g[1][tid+2] + vh3*g[1][tid+3] + vh4*g[1][tid+4];
    b[0][1 + tid] = bh1;
    b[1][1 + tid] = bh254;
    __syncthreads();

    // E(0) = -sh*b1, E(255) = +sh*b254 (blurred col halo is zero)
    float e0   = -(sh0*b[0][tid] + sh1*b[0][tid+1] + sh2*b[0][tid+2]);
    float e255 =  (sh0*b[1][tid] + sh1*b[1][tid+1] + sh2*b[1][tid+2]);

    int miss = (e0 == 0.f) || (e255 == 0.f);
    bool fast = (__syncthreads_count(miss) == 0);

    if (fast) {
        // Every column has nonzero edge on rows 0 and 255 -> bbox = full tile
        // (after +-2 dilation clipped to the tile).
        if (tid == 0) {
            atomicMax(&dstate[slot*4 + 0], y0 + 256);
            atomicMax(&dstate[slot*4 + 1], 4096 - y0);
            atomicMax(&dstate[slot*4 + 2], x0 + 256);
            atomicMax(&dstate[slot*4 + 3], 4096 - x0);
        }
    } else {
        // ---------------- GENERIC FALLBACK (rare/never on this data) --------
        float gk[25];
        #pragma unroll
        for (int t = 0; t < 25; ++t) gk[t] = gauss[t];
        float sk[9];
        #pragma unroll
        for (int t = 0; t < 9; ++t) sk[t] = sobel[t];

        auto compute_row = [&](int i) -> float {
            for (int rr = 0; rr < 7; ++rr) {
                int r = i - 3 + rr;
                float v = 0.f;
                if ((unsigned)r < 256u) {
                    int off = (y0 + r) * W + (x0 + tid);
                    v = w0 * x[off] + w1 * x[off + CHOFF] + w2 * x[off + 2 * CHOFF];
                }
                g[rr][2 + tid] = v;
            }
            __syncthreads();
            #pragma unroll
            for (int k = 0; k < 3; ++k) {
                int r = i - 1 + k;
                float bb = 0.f;
                if ((unsigned)r < 256u) {
                    #pragma unroll
                    for (int a = 0; a < 5; ++a)
                        #pragma unroll
                        for (int c = 0; c < 5; ++c)
                            bb += gk[a * 5 + c] * g[k + a][tid + c];
                }
                b[k][1 + tid] = bb;
            }
            __syncthreads();
            float e = 0.f;
            #pragma unroll
            for (int a = 0; a < 3; ++a)
                #pragma unroll
                for (int c = 0; c < 3; ++c)
                    e += sk[a * 3 + c] * b[a][tid + c];
            return e;
        };

        bool has = false;
        int firstRow = 0, lastRow = -1;
        int T_stop = -1;
        bool exhausted = true;

        for (int i = 0; i < 256; ++i) {
            float e = compute_row(i);
            if (e != 0.f) {
                if (!has) { has = true; firstRow = i; }
                lastRow = i;
            }
            if (__syncthreads_count(has ? 0 : 1) == 0) {
                T_stop = i; exhausted = false; break;
            }
        }
        if (!exhausted && T_stop < 255) {
            bool bot = false;
            for (int i = 255; i > T_stop; --i) {
                float e = compute_row(i);
                if (e != 0.f) {
                    bot = true;
                    if (i > lastRow) lastRow = i;
                }
                if (__syncthreads_count(bot ? 0 : 1) == 0) break;
            }
        }

        int vF  = has ? firstRow : INT_MAX;
        int vL  = lastRow;
        int vMn = has ? tid : INT_MAX;
        int vMx = has ? tid : -1;
        const unsigned FULL = 0xffffffffu;
        vF  = __reduce_min_sync(FULL, vF);
        vL  = __reduce_max_sync(FULL, vL);
        vMn = __reduce_min_sync(FULL, vMn);
        vMx = __reduce_max_sync(FULL, vMx);
        int wid = tid >> 5, lane = tid & 31;
        if (lane == 0) { sF[wid] = vF; sL[wid] = vL; sMn[wid] = vMn; sMx[wid] = vMx; }
        __syncthreads();
        if (tid == 0) {
            int f = INT_MAX, l = -1, mn = INT_MAX, mx = -1;
            #pragma unroll
            for (int k = 0; k < 8; ++k) {
                f  = min(f,  sF[k]);
                l  = max(l,  sL[k]);
                mn = min(mn, sMn[k]);
                mx = max(mx, sMx[k]);
            }
            if (l >= 0) {
                atomicMax(&dstate[slot*4 + 0], y0 + min(255, l + 2) + 1);
                atomicMax(&dstate[slot*4 + 1], 4096 - (y0 + max(0, f - 2)));
                atomicMax(&dstate[slot*4 + 2], x0 + min(255, mx + 2) + 1);
                atomicMax(&dstate[slot*4 + 3], 4096 - (x0 + max(0, mn - 2)));
            }
        }
    }

    // ---------------- hierarchical LAST-BLOCK FINALIZE ----------------
    if (tid == 0) {
        __threadfence();
        if (atomicAdd(&dstate[D_CNT + slot], 1) == NSLOT - 1) {   // last in slot
            if (atomicAdd(&dstate[D_MST], 1) == NSLOT - 1) {      // last slot
                __threadfence();
                int ymaxp = 0, yminC = 0, xmaxp = 0, xminC = 0;
                #pragma unroll 1
                for (int s = 0; s < NSLOT; ++s) {
                    // atomic reads -> L2-coherent
                    ymaxp = max(ymaxp, atomicMax(&dstate[s*4 + 0], 0));
                    yminC = max(yminC, atomicMax(&dstate[s*4 + 1], 0));
                    xmaxp = max(xmaxp, atomicMax(&dstate[s*4 + 2], 0));
                    xminC = max(xminC, atomicMax(&dstate[s*4 + 3], 0));
                }
                if (ymaxp == 0) {
                    out[0] = 0.f; out[1] = 0.f; out[2] = 0.f; out[3] = 0.f;
                } else {
                    out[0] = (float)(4096 - xminC);  // x_min
                    out[1] = (float)(4096 - yminC);  // y_min
                    out[2] = (float)xmaxp;           // x_max
                    out[3] = (float)ymaxp;           // y_max
                }
            }
        }
    }
}

extern "C" void kernel_launch(void* const* d_in, const int* in_sizes, int n_in,
                              void* d_out, int out_size)
{
    const float* x     = (const float*)d_in[0];
    const float* gw    = (const float*)d_in[1];
    const float* gauss = (const float*)d_in[2];
    const float* sobel = (const float*)d_in[3];

    void* sym = nullptr;
    cudaGetSymbolAddress(&sym, dstate);
    cudaMemsetAsync(sym, 0, sizeof(dstate));

    tile_kernel<<<NBLOCKS, 256>>>(x, gw, gauss, sobel, (float*)d_out);
}

// round 4
// speedup vs baseline: 1.9352x; 1.9352x over previous
#include <cuda_runtime.h>
#include <climits>

// Problem constants (fixed by reference setup_inputs)
#define W       4096
#define CHOFF   (4096 * 4096)
#define NT      31          // ceil((4096-256)/128)+1
#define STRIDE  128
#define NBLOCKS (NT * NT)   // 961

// Encoded bbox accumulators, all atomicMax with init 0 (one memset):
//  dstate[0] = max(ymax+1)       dstate[1] = max(4096 - ymin)
//  dstate[2] = max(xmax+1)       dstate[3] = max(4096 - xmin)
//  dstate[4] = completion counter
__device__ int dstate[5];

__global__ __launch_bounds__(256) void tile_kernel(
    const float* __restrict__ x,
    const float* __restrict__ gw,
    const float* __restrict__ gauss,
    const float* __restrict__ sobel,
    float* __restrict__ out)
{
    __shared__ float g[7][260];   // gray rows, col halo +-2 (zero pad)
    __shared__ float b[3][258];   // blurred rows, col halo +-1 (zero pad)
    __shared__ int sF[8], sL[8], sMn[8], sMx[8];

    const int tid = threadIdx.x;
    const int ty  = blockIdx.x / NT;
    const int tx  = blockIdx.x % NT;
    const int y0  = ty * STRIDE;
    const int x0  = tx * STRIDE;

    const float w0 = gw[0], w1 = gw[1], w2 = gw[2];
    // Separable factors (exact: gauss = (uv ⊗ vh), uv = col0/gauss[0] = [1,4,6,4,1])
    const float ginv = 1.0f / gauss[0];
    const float uv1 = gauss[5]  * ginv;   // 4
    const float uv2 = gauss[10] * ginv;   // 6
    const float uv3 = gauss[15] * ginv;   // 4
    const float vh0 = gauss[0], vh1 = gauss[1], vh2 = gauss[2], vh3 = gauss[3], vh4 = gauss[4];
    const float sh0 = sobel[0], sh1 = sobel[1], sh2 = sobel[2];  // [1,2,1]

    // Static zero halos (per-tile zero padding; never overwritten)
    if (tid < 2) {
        #pragma unroll
        for (int rr = 0; rr < 7; ++rr) { g[rr][tid] = 0.f; g[rr][258 + tid] = 0.f; }
    }
    if (tid == 0) {
        #pragma unroll
        for (int k = 0; k < 3; ++k) { b[k][0] = 0.f; b[k][257] = 0.f; }
    }

    // ---------------- FAST PATH ----------------
    // Sobel middle row is 0, so E(0) = -sh * blurred(1), E(255) = +sh * blurred(254).
    // blurred(1) needs gray rows 0..3; blurred(254) needs gray rows 252..255.
    // Vertical gauss in registers; horizontal gauss via one smem exchange.
    {
        const int base  = y0 * W + x0 + tid;
        const int base2 = base + 252 * W;
        float bv1 = 0.f, bv254 = 0.f;
        #pragma unroll
        for (int rr = 0; rr < 4; ++rr) {
            int off = base + rr * W;
            float gr = w0 * x[off] + w1 * x[off + CHOFF] + w2 * x[off + 2 * CHOFF];
            // vertical taps for blurred row 1: rows -1..3 -> taps uv[rr+1] for rr=0..3
            float tap1 = (rr == 0) ? uv1 : (rr == 1) ? uv2 : (rr == 2) ? uv3 : 1.f;
            bv1 += tap1 * gr;
            int off2 = base2 + rr * W;
            float gr2 = w0 * x[off2] + w1 * x[off2 + CHOFF] + w2 * x[off2 + 2 * CHOFF];
            // vertical taps for blurred row 254: rows 252..256 -> taps uv[rr] for rr=0..3
            float tap2 = (rr == 0) ? 1.f : (rr == 1) ? uv1 : (rr == 2) ? uv2 : uv3;
            bv254 += tap2 * gr2;
        }
        g[0][2 + tid] = bv1;
        g[1][2 + tid] = bv254;
    }
    __syncthreads();

    float bh1   = vh0*g[0][tid] + vh1*g[0][tid+1] + vh2*g[0][tid+2] + vh3*g[0][tid+3] + vh4*g[0][tid+4];
    float bh254 = vh0*g[1][tid] + vh1*g[1][tid+1] + vh2*g[1][tid+2] + vh3*g[1][tid+3] + vh4*g[1][tid+4];
    b[0][1 + tid] = bh1;
    b[1][1 + tid] = bh254;
    __syncthreads();

    float e0   = -(sh0*b[0][tid] + sh1*b[0][tid+1] + sh2*b[0][tid+2]);
    float e255 =  (sh0*b[1][tid] + sh1*b[1][tid+1] + sh2*b[1][tid+2]);

    int miss = (e0 == 0.f) || (e255 == 0.f);
    bool fast = (__syncthreads_count(miss) == 0);

    if (fast) {
        // Every column has a nonzero edge on rows 0 and 255 -> bbox of {E!=0}
        // spans the full tile; +-2 dilation clipped to the tile = full tile.
        if (tid == 0) {
            atomicMax(&dstate[0], y0 + 256);
            atomicMax(&dstate[1], 4096 - y0);
            atomicMax(&dstate[2], x0 + 256);
            atomicMax(&dstate[3], 4096 - x0);
        }
    } else {
        // ---------------- GENERIC FALLBACK (rare/never on this data) --------
        float gk[25];
        #pragma unroll
        for (int t = 0; t < 25; ++t) gk[t] = gauss[t];
        float sk[9];
        #pragma unroll
        for (int t = 0; t < 9; ++t) sk[t] = sobel[t];

        auto compute_row = [&](int i) -> float {
            for (int rr = 0; rr < 7; ++rr) {
                int r = i - 3 + rr;
                float v = 0.f;
                if ((unsigned)r < 256u) {
                    int off = (y0 + r) * W + (x0 + tid);
                    v = w0 * x[off] + w1 * x[off + CHOFF] + w2 * x[off + 2 * CHOFF];
                }
                g[rr][2 + tid] = v;
            }
            __syncthreads();
            #pragma unroll
            for (int k = 0; k < 3; ++k) {
                int r = i - 1 + k;
                float bb = 0.f;
                if ((unsigned)r < 256u) {
                    #pragma unroll
                    for (int a = 0; a < 5; ++a)
                        #pragma unroll
                        for (int c = 0; c < 5; ++c)
                            bb += gk[a * 5 + c] * g[k + a][tid + c];
                }
                b[k][1 + tid] = bb;
            }
            __syncthreads();
            float e = 0.f;
            #pragma unroll
            for (int a = 0; a < 3; ++a)
                #pragma unroll
                for (int c = 0; c < 3; ++c)
                    e += sk[a * 3 + c] * b[a][tid + c];
            return e;
        };

        bool has = false;
        int firstRow = 0, lastRow = -1;
        int T_stop = -1;
        bool exhausted = true;

        __syncthreads();  // protect smem reuse after fast-path reads
        for (int i = 0; i < 256; ++i) {
            float e = compute_row(i);
            if (e != 0.f) {
                if (!has) { has = true; firstRow = i; }
                lastRow = i;
            }
            if (__syncthreads_count(has ? 0 : 1) == 0) {
                T_stop = i; exhausted = false; break;
            }
        }
        if (!exhausted && T_stop < 255) {
            bool bot = false;
            for (int i = 255; i > T_stop; --i) {
                float e = compute_row(i);
                if (e != 0.f) {
                    bot = true;
                    if (i > lastRow) lastRow = i;
                }
                if (__syncthreads_count(bot ? 0 : 1) == 0) break;
            }
        }

        int vF  = has ? firstRow : INT_MAX;
        int vL  = lastRow;
        int vMn = has ? tid : INT_MAX;
        int vMx = has ? tid : -1;
        const unsigned FULL = 0xffffffffu;
        vF  = __reduce_min_sync(FULL, vF);
        vL  = __reduce_max_sync(FULL, vL);
        vMn = __reduce_min_sync(FULL, vMn);
        vMx = __reduce_max_sync(FULL, vMx);
        int wid = tid >> 5, lane = tid & 31;
        if (lane == 0) { sF[wid] = vF; sL[wid] = vL; sMn[wid] = vMn; sMx[wid] = vMx; }
        __syncthreads();
        if (tid == 0) {
            int f = INT_MAX, l = -1, mn = INT_MAX, mx = -1;
            #pragma unroll
            for (int k = 0; k < 8; ++k) {
                f  = min(f,  sF[k]);
                l  = max(l,  sL[k]);
                mn = min(mn, sMn[k]);
                mx = max(mx, sMx[k]);
            }
            if (l >= 0) {
                atomicMax(&dstate[0], y0 + min(255, l + 2) + 1);
                atomicMax(&dstate[1], 4096 - (y0 + max(0, f - 2)));
                atomicMax(&dstate[2], x0 + min(255, mx + 2) + 1);
                atomicMax(&dstate[3], 4096 - (x0 + max(0, mn - 2)));
            }
        }
    }

    // ---------------- LAST-BLOCK FINALIZE ----------------
    if (tid == 0) {
        __threadfence();
        int prev = atomicAdd(&dstate[4], 1);
        if (prev == NBLOCKS - 1) {
            __threadfence();
            int ymaxp = dstate[0];
            if (ymaxp == 0) {
                out[0] = 0.f; out[1] = 0.f; out[2] = 0.f; out[3] = 0.f;
            } else {
                out[0] = (float)(4096 - dstate[3]);  // x_min
                out[1] = (float)(4096 - dstate[1]);  // y_min
                out[2] = (float)dstate[2];           // x_max
                out[3] = (float)ymaxp;               // y_max
            }
        }
    }
}

extern "C" void kernel_launch(void* const* d_in, const int* in_sizes, int n_in,
                              void* d_out, int out_size)
{
    const float* x     = (const float*)d_in[0];
    const float* gw    = (const float*)d_in[1];
    const float* gauss = (const float*)d_in[2];
    const float* sobel = (const float*)d_in[3];

    void* sym = nullptr;
    cudaGetSymbolAddress(&sym, dstate);
    cudaMemsetAsync(sym, 0, sizeof(dstate));

    tile_kernel<<<NBLOCKS, 256>>>(x, gw, gauss, sobel, (float*)d_out);
}